// round 7
// baseline (speedup 1.0000x reference)
#include <cuda_runtime.h>
#include <cuda_bf16.h>
#include <math.h>
#include <stdint.h>

// Problem dims
#define Bsz 512
#define Tsz 512
#define Lsz 64
#define Hsz 512
#define H3  1536                // 3*H
#define XW  (Tsz + Lsz - 1)     // 575

// ---------------- scratch (__device__ globals; no cudaMalloc) --------------
__device__ float g_GI1[(size_t)Lsz * Bsz * H3];  // [L*B][3H] fp32 (~201MB)
__device__ float g_GH1[Bsz * H3];                // prologue only
__device__ float g_GI2[Bsz * H3];
__device__ float g_GH2[Bsz * H3];
__device__ float g_H1[Bsz * Hsz];
__device__ float g_H2[Bsz * Hsz];

// split-bf16 planes (hi/lo); H1 planes are ping-ponged (2 copies)
__device__ __align__(256) __nv_bfloat16 g_Whh1h[H3 * Hsz], g_Whh1l[H3 * Hsz];
__device__ __align__(256) __nv_bfloat16 g_Wih2h[H3 * Hsz], g_Wih2l[H3 * Hsz];
__device__ __align__(256) __nv_bfloat16 g_Whh2h[H3 * Hsz], g_Whh2l[H3 * Hsz];
__device__ __align__(256) __nv_bfloat16 g_Wih1h[H3 * Hsz], g_Wih1l[H3 * Hsz];
__device__ __align__(256) __nv_bfloat16 g_H1h[2 * Bsz * Hsz], g_H1l[2 * Bsz * Hsz];
__device__ __align__(256) __nv_bfloat16 g_H2h[Bsz * Hsz], g_H2l[Bsz * Hsz];
// windowed x, split planes: [L*B][512]
__device__ __align__(256) __nv_bfloat16 g_Axh[(size_t)Lsz * Bsz * Hsz];
__device__ __align__(256) __nv_bfloat16 g_Axl[(size_t)Lsz * Bsz * Hsz];

// ---------------- helpers ---------------------------------------------------
__device__ __forceinline__ uint32_t smem_u32(const void* p) {
    uint32_t a;
    asm("{ .reg .u64 t; cvta.to.shared.u64 t, %1; cvt.u32.u64 %0, t; }"
        : "=r"(a) : "l"(p));
    return a;
}
__device__ __forceinline__ void cp16(uint32_t dst, const void* src) {
    asm volatile("cp.async.cg.shared.global [%0], [%1], 16;" :: "r"(dst), "l"(src));
}
__device__ __forceinline__ void ldsm4(uint32_t& r0, uint32_t& r1, uint32_t& r2, uint32_t& r3,
                                      uint32_t addr) {
    asm volatile("ldmatrix.sync.aligned.m8n8.x4.shared.b16 {%0,%1,%2,%3}, [%4];"
                 : "=r"(r0), "=r"(r1), "=r"(r2), "=r"(r3) : "r"(addr));
}
__device__ __forceinline__ void mma16816(float* c, const uint32_t* a, const uint32_t* b) {
    asm volatile(
        "mma.sync.aligned.m16n8k16.row.col.f32.bf16.bf16.f32 "
        "{%0,%1,%2,%3}, {%4,%5,%6,%7}, {%8,%9}, {%0,%1,%2,%3};"
        : "+f"(c[0]), "+f"(c[1]), "+f"(c[2]), "+f"(c[3])
        : "r"(a[0]), "r"(a[1]), "r"(a[2]), "r"(a[3]), "r"(b[0]), "r"(b[1]));
}
__device__ __forceinline__ float sigmoidf_(float v) {
    return 1.f / (1.f + __expf(-v));
}
__device__ __forceinline__ void split_store(float v, __nv_bfloat16* hp, __nv_bfloat16* lp, size_t i) {
    __nv_bfloat16 h = __float2bfloat16(v);
    hp[i] = h;
    lp[i] = __float2bfloat16(v - __bfloat162float(h));
}

// smem tile row: 32 bf16 (64B data), stride 80B -> ldmatrix conflict-free.
#define TROW   80
#define STAGES 3

// ---------------- split-bf16 GEMM core (mma.sync, 3-stage pipeline) ---------
// D[TM x 128] = sum_{K'=1536} A'(TM x K') * B'(128 x K')^T + bias
// segments of 512: 0:(Ah,Bh) 1:(Al,Bh) 2:(Ah,Bl); 48 chunks of BK=32.
template<int TM>
__device__ __forceinline__ void gemm_mma(
    const __nv_bfloat16* __restrict__ Ah, const __nv_bfloat16* __restrict__ Al, int m0,
    const __nv_bfloat16* __restrict__ Bh, const __nv_bfloat16* __restrict__ Bl, int n0,
    const float* __restrict__ bias, float* __restrict__ C, int ldc)
{
    extern __shared__ __align__(16) char smraw[];
    constexpr int ATILE = TM * TROW;
    constexpr int BTILE = 128 * TROW;
    constexpr int MA    = TM / 32;
    const uint32_t sA = smem_u32(smraw);
    const uint32_t sB = sA + STAGES * ATILE;

    const int tid  = threadIdx.x;
    const int wid  = tid >> 5;
    const int lane = tid & 31;
    const int wm0  = (wid & 1) * (TM / 2);
    const int wn0  = (wid >> 1) * 32;

    const int qrow = tid >> 2;
    const int qk   = tid & 3;

    float acc[MA][4][4];
#pragma unroll
    for (int mi = 0; mi < MA; mi++)
#pragma unroll
        for (int ni = 0; ni < 4; ni++)
#pragma unroll
            for (int j = 0; j < 4; j++) acc[mi][ni][j] = 0.f;

    auto issue = [&](int c, int st) {
        const int seg = c >> 4;
        const int kk  = (c & 15) * 32;
        const __nv_bfloat16* As = (seg == 1) ? Al : Ah;
        const __nv_bfloat16* Bs = (seg == 2) ? Bl : Bh;
#pragma unroll
        for (int r = 0; r < TM; r += 64)
            cp16(sA + st * ATILE + (qrow + r) * TROW + qk * 16,
                 As + (size_t)(m0 + qrow + r) * Hsz + kk + qk * 8);
#pragma unroll
        for (int r = 0; r < 128; r += 64)
            cp16(sB + st * BTILE + (qrow + r) * TROW + qk * 16,
                 Bs + (size_t)(n0 + qrow + r) * Hsz + kk + qk * 8);
        asm volatile("cp.async.commit_group;");
    };

    issue(0, 0);
    issue(1, 1);

    for (int c = 0; c < 48; c++) {
        const int st = c % STAGES;
        if (c < 47) asm volatile("cp.async.wait_group 1;");
        else        asm volatile("cp.async.wait_group 0;");
        __syncthreads();
        if (c + 2 < 48) issue(c + 2, (c + 2) % STAGES);

        const uint32_t bufA = sA + st * ATILE;
        const uint32_t bufB = sB + st * BTILE;
#pragma unroll
        for (int kb = 0; kb < 32; kb += 16) {
            uint32_t a[MA][4];
#pragma unroll
            for (int mi = 0; mi < MA; mi++) {
                uint32_t addr = bufA + (wm0 + mi * 16 + (lane & 15)) * TROW
                              + (kb + ((lane >> 4) << 3)) * 2;
                ldsm4(a[mi][0], a[mi][1], a[mi][2], a[mi][3], addr);
            }
            uint32_t b[4][2];
#pragma unroll
            for (int nb = 0; nb < 2; nb++) {
                uint32_t addr = bufB
                              + (wn0 + nb * 16 + (lane & 7) + ((lane >> 4) << 3)) * TROW
                              + (kb + ((lane >> 3) & 1) * 8) * 2;
                uint32_t r0, r1, r2, r3;
                ldsm4(r0, r1, r2, r3, addr);
                b[nb * 2][0] = r0;     b[nb * 2][1] = r1;
                b[nb * 2 + 1][0] = r2; b[nb * 2 + 1][1] = r3;
            }
#pragma unroll
            for (int mi = 0; mi < MA; mi++)
#pragma unroll
                for (int ni = 0; ni < 4; ni++)
                    mma16816(acc[mi][ni], a[mi], b[ni]);
        }
    }

#pragma unroll
    for (int mi = 0; mi < MA; mi++) {
#pragma unroll
        for (int ni = 0; ni < 4; ni++) {
            int r   = m0 + wm0 + mi * 16 + (lane >> 2);
            int cix = n0 + wn0 + ni * 8 + (lane & 3) * 2;
            float b0 = bias[cix], b1 = bias[cix + 1];
            *(float2*)&C[(size_t)r * ldc + cix] =
                make_float2(acc[mi][ni][0] + b0, acc[mi][ni][1] + b1);
            *(float2*)&C[(size_t)(r + 8) * ldc + cix] =
                make_float2(acc[mi][ni][2] + b0, acc[mi][ni][3] + b1);
        }
    }
}

#define SMEM128 (STAGES * (128 * TROW) * 2)              // 61440 (gi1/gh1)
#define SMEM_Z0 (STAGES * ((32 + 384) * TROW))           // 99840 (step kernel)

// ---------------- z0 core: 32x384 interleaved-gate GEMM + GRU-1 epilogue ----
// Computes GH1 = H1(pp) @ Whh1^T for N-cols {bx*128+c, 512+.., 1024+..},
// then applies layer-1 gates for step t+1 and writes H1(t+1) into plane pp^1.
__device__ __forceinline__ void z0_core(
    int by, int bx, int pp, int t,
    const float* __restrict__ bhh1)
{
    extern __shared__ __align__(16) char smraw[];
    const int m0 = by * 32;
    const uint32_t sA = smem_u32(smraw);
    const uint32_t sB = sA + STAGES * (32 * TROW);
    constexpr int ATILE = 32 * TROW;
    constexpr int BTILE = 384 * TROW;

    const __nv_bfloat16* Ah = g_H1h + (size_t)pp * Bsz * Hsz;
    const __nv_bfloat16* Al = g_H1l + (size_t)pp * Bsz * Hsz;

    const int tid  = threadIdx.x;
    const int wid  = tid >> 5;
    const int lane = tid & 31;
    const int wn0  = wid * 48;          // 8 warps across N=384

    const int qrow = tid >> 2;          // 0..63
    const int qk   = tid & 3;

    float acc[2][6][4];
#pragma unroll
    for (int mi = 0; mi < 2; mi++)
#pragma unroll
        for (int ni = 0; ni < 6; ni++)
#pragma unroll
            for (int j = 0; j < 4; j++) acc[mi][ni][j] = 0.f;

    auto issue = [&](int c, int st) {
        const int seg = c >> 4;
        const int kk  = (c & 15) * 32;
        const __nv_bfloat16* As = (seg == 1) ? Al : Ah;
        const __nv_bfloat16* Bs = (seg == 2) ? g_Whh1l : g_Whh1h;
        if (tid < 128)
            cp16(sA + st * ATILE + qrow * TROW + qk * 16,
                 As + (size_t)(m0 + qrow) * Hsz + kk + qk * 8);
#pragma unroll
        for (int rep = 0; rep < 6; rep++) {
            int row = qrow + rep * 64;                        // 0..383
            int g   = row >> 7;
            int wr  = g * 512 + bx * 128 + (row & 127);       // global W row
            cp16(sB + st * BTILE + row * TROW + qk * 16,
                 Bs + (size_t)wr * Hsz + kk + qk * 8);
        }
        asm volatile("cp.async.commit_group;");
    };

    issue(0, 0);
    issue(1, 1);

    for (int c = 0; c < 48; c++) {
        const int st = c % STAGES;
        if (c < 47) asm volatile("cp.async.wait_group 1;");
        else        asm volatile("cp.async.wait_group 0;");
        __syncthreads();
        if (c + 2 < 48) issue(c + 2, (c + 2) % STAGES);

        const uint32_t bufA = sA + st * ATILE;
        const uint32_t bufB = sB + st * BTILE;
#pragma unroll
        for (int kb = 0; kb < 32; kb += 16) {
            uint32_t a[2][4];
#pragma unroll
            for (int mi = 0; mi < 2; mi++) {
                uint32_t addr = bufA + (mi * 16 + (lane & 15)) * TROW
                              + (kb + ((lane >> 4) << 3)) * 2;
                ldsm4(a[mi][0], a[mi][1], a[mi][2], a[mi][3], addr);
            }
#pragma unroll
            for (int nb = 0; nb < 3; nb++) {
                uint32_t addr = bufB
                              + (wn0 + nb * 16 + (lane & 7) + ((lane >> 4) << 3)) * TROW
                              + (kb + ((lane >> 3) & 1) * 8) * 2;
                uint32_t r0, r1, r2, r3;
                ldsm4(r0, r1, r2, r3, addr);
                uint32_t blo[2] = { r0, r1 }, bhi[2] = { r2, r3 };
#pragma unroll
                for (int mi = 0; mi < 2; mi++) {
                    mma16816(acc[mi][nb * 2],     a[mi], blo);
                    mma16816(acc[mi][nb * 2 + 1], a[mi], bhi);
                }
            }
        }
    }

    // stage accumulator (32 x 384 fp32) into smem
    __syncthreads();
    float* stg = (float*)smraw;
#pragma unroll
    for (int mi = 0; mi < 2; mi++) {
#pragma unroll
        for (int ni = 0; ni < 6; ni++) {
            int r = mi * 16 + (lane >> 2);
            int c = wn0 + ni * 8 + (lane & 3) * 2;
            stg[r * 384 + c]       = acc[mi][ni][0];
            stg[r * 384 + c + 1]   = acc[mi][ni][1];
            stg[(r + 8) * 384 + c]     = acc[mi][ni][2];
            stg[(r + 8) * 384 + c + 1] = acc[mi][ni][3];
        }
    }
    __syncthreads();

    // GRU layer-1 gates for step t+1
    const __nv_bfloat16* dsth = g_H1h + (size_t)(pp ^ 1) * Bsz * Hsz;
    const __nv_bfloat16* dstl = g_H1l + (size_t)(pp ^ 1) * Bsz * Hsz;
#pragma unroll
    for (int rep = 0; rep < 16; rep++) {
        int idx = tid + rep * 256;
        int r   = idx >> 7;              // 0..31
        int jc  = idx & 127;
        int m   = m0 + r;
        int j   = bx * 128 + jc;
        float ghr = stg[r * 384 + jc]        + bhh1[j];
        float ghz = stg[r * 384 + 128 + jc]  + bhh1[512 + j];
        float ghn = stg[r * 384 + 256 + jc]  + bhh1[1024 + j];
        const float* gi = g_GI1 + ((size_t)(t + 1) * Bsz + m) * H3;
        float rr = sigmoidf_(gi[j]        + ghr);
        float zz = sigmoidf_(gi[512 + j]  + ghz);
        float nn = tanhf   (gi[1024 + j] + rr * ghn);
        size_t hi = (size_t)m * Hsz + j;
        float h = g_H1[hi];
        float hnew = (1.f - zz) * nn + zz * h;
        g_H1[hi] = hnew;
        split_store(hnew, (__nv_bfloat16*)dsth, (__nv_bfloat16*)dstl, hi);
    }
}

// ---------------- GEMM wrappers --------------------------------------------
__global__ void __launch_bounds__(256, 2)
k_gi1_tc(const float* __restrict__ bih1)
{
    gemm_mma<128>(g_Axh, g_Axl, blockIdx.y * 128,
                  g_Wih1h, g_Wih1l, blockIdx.x * 128,
                  bih1, g_GI1, H3);
}

__global__ void __launch_bounds__(256, 2)
k_gh1_tc(const float* __restrict__ bhh1)
{
    gemm_mma<128>(g_H1h, g_H1l, blockIdx.y * 128,   // plane 0
                  g_Whh1h, g_Whh1l, blockIdx.x * 128,
                  bhh1, g_GH1, H3);
}

// per-step fused kernel, flat grid of 256 CTAs:
//  bid [0,64):    z0  (32x384 GH1 GEMM + fused gates1(t+1)), skipped at t=63
//  bid [64,160):  z1  GI2 = H1(pp) @ Wih2^T   (64x128 tiles)
//  bid [160,256): z2  GH2 = H2 @ Whh2^T       (64x128 tiles)
__global__ void __launch_bounds__(256, 2)
k_gemm3_tc(int pp, int t,
           const float* __restrict__ bhh1, const float* __restrict__ bih2,
           const float* __restrict__ bhh2)
{
    int bid = blockIdx.x;
    if (bid < 64) {
        if (t == Lsz - 1) return;        // GH1(64)/gates1(64) not needed
        z0_core(bid >> 2, bid & 3, pp, t, bhh1);
        return;
    }
    int i  = bid - 64;
    int z  = i / 96;
    i      = i % 96;
    int bx = i % 12, by = i / 12;
    if (z == 0) {
        gemm_mma<64>(g_H1h + (size_t)pp * Bsz * Hsz, g_H1l + (size_t)pp * Bsz * Hsz,
                     by * 64, g_Wih2h, g_Wih2l, bx * 128, bih2, g_GI2, H3);
    } else {
        gemm_mma<64>(g_H2h, g_H2l, by * 64,
                     g_Whh2h, g_Whh2l, bx * 128, bhh2, g_GH2, H3);
    }
}

// ---------------- elementwise ----------------------------------------------
// prologue-only layer-1 gates for t=0 (reads GH1, writes H1 + plane 0)
__global__ void k_gates1(void)
{
    int b = blockIdx.x, j = threadIdx.x;
    const float* gi = g_GI1 + (size_t)b * H3;
    const float* gh = g_GH1 + (size_t)b * H3;
    float r = sigmoidf_(gi[j]           + gh[j]);
    float z = sigmoidf_(gi[Hsz + j]     + gh[Hsz + j]);
    float n = tanhf   (gi[2 * Hsz + j] + r * gh[2 * Hsz + j]);
    size_t hi = (size_t)b * Hsz + j;
    float h = g_H1[hi];
    float hnew = (1.f - z) * n + z * h;
    g_H1[hi] = hnew;
    split_store(hnew, g_H1h, g_H1l, hi);    // plane 0
}

// layer-2 gates + fc output for step t
__global__ void k_gates2(int t, const float* __restrict__ Wfc,
                         const float* __restrict__ bfc, float* __restrict__ out)
{
    __shared__ float red[16];
    int b = blockIdx.x, j = threadIdx.x;
    int lane = j & 31, wid = j >> 5;
    size_t hi = (size_t)b * Hsz + j;

    const float* gi = g_GI2 + (size_t)b * H3;
    const float* gh = g_GH2 + (size_t)b * H3;
    float r = sigmoidf_(gi[j]           + gh[j]);
    float z = sigmoidf_(gi[Hsz + j]     + gh[Hsz + j]);
    float n = tanhf   (gi[2 * Hsz + j] + r * gh[2 * Hsz + j]);
    float h = g_H2[hi];
    float hnew = (1.f - z) * n + z * h;
    g_H2[hi] = hnew;
    split_store(hnew, g_H2h, g_H2l, hi);

    float v = hnew * Wfc[j];
#pragma unroll
    for (int s = 16; s > 0; s >>= 1) v += __shfl_down_sync(0xffffffffu, v, s);
    if (lane == 0) red[wid] = v;
    __syncthreads();
    if (wid == 0) {
        float vv = (lane < 16) ? red[lane] : 0.f;
#pragma unroll
        for (int s = 8; s > 0; s >>= 1) vv += __shfl_down_sync(0xffffffffu, vv, s);
        if (lane == 0) out[(size_t)b * Lsz + t] = vv + bfc[0];
    }
}

// ---------------- conversions ----------------------------------------------
__global__ void k_split_w(const float* __restrict__ Whh1, const float* __restrict__ Wih2,
                          const float* __restrict__ Whh2, const float* __restrict__ Wih1)
{
    int i = blockIdx.x * blockDim.x + threadIdx.x;
    if (i >= H3 * Hsz) return;
    split_store(Whh1[i], g_Whh1h, g_Whh1l, i);
    split_store(Wih2[i], g_Wih2h, g_Wih2l, i);
    split_store(Whh2[i], g_Whh2h, g_Whh2l, i);
    split_store(Wih1[i], g_Wih1h, g_Wih1l, i);
}

__global__ void k_convx(const float* __restrict__ x)
{
    long long i = blockIdx.x * (long long)blockDim.x + threadIdx.x;
    if (i >= (long long)Lsz * Bsz * Hsz) return;
    int k   = (int)(i & 511);
    int rem = (int)(i >> 9);
    int b   = rem & 511;
    int l   = rem >> 9;
    float v = x[(size_t)b * XW + l + k];
    split_store(v, g_Axh, g_Axl, (size_t)i);
}

__global__ void k_init(const float* __restrict__ h1in, const float* __restrict__ h2in)
{
    int i = blockIdx.x * blockDim.x + threadIdx.x;
    if (i < Bsz * Hsz) {
        float v1 = h1in[i], v2 = h2in[i];
        g_H1[i] = v1; g_H2[i] = v2;
        split_store(v1, g_H1h, g_H1l, i);   // plane 0
        split_store(v2, g_H2h, g_H2l, i);
    }
}

__global__ void k_copyout(float* __restrict__ out, int out_size)
{
    int i = blockIdx.x * blockDim.x + threadIdx.x;
    const int yN = Bsz * Lsz, hN = Bsz * Hsz;
    if (yN + 2 * hN <= out_size && i < hN) {
        out[yN + i]      = g_H1[i];
        out[yN + hN + i] = g_H2[i];
    }
}

// ---------------- launch ----------------------------------------------------
extern "C" void kernel_launch(void* const* d_in, const int* in_sizes, int n_in,
                              void* d_out, int out_size)
{
    const float* x    = (const float*)d_in[0];
    const float* h1in = (const float*)d_in[1];
    const float* h2in = (const float*)d_in[2];
    const float* Wih1 = (const float*)d_in[3];
    const float* Whh1 = (const float*)d_in[4];
    const float* bih1 = (const float*)d_in[5];
    const float* bhh1 = (const float*)d_in[6];
    const float* Wih2 = (const float*)d_in[7];
    const float* Whh2 = (const float*)d_in[8];
    const float* bih2 = (const float*)d_in[9];
    const float* bhh2 = (const float*)d_in[10];
    const float* Wfc  = (const float*)d_in[11];
    const float* bfc  = (const float*)d_in[12];
    float* out = (float*)d_out;

    cudaFuncSetAttribute(k_gi1_tc,   cudaFuncAttributeMaxDynamicSharedMemorySize, SMEM128);
    cudaFuncSetAttribute(k_gh1_tc,   cudaFuncAttributeMaxDynamicSharedMemorySize, SMEM128);
    cudaFuncSetAttribute(k_gemm3_tc, cudaFuncAttributeMaxDynamicSharedMemorySize, SMEM_Z0);

    k_init<<<(Bsz * Hsz + 255) / 256, 256>>>(h1in, h2in);
    k_split_w<<<(H3 * Hsz + 255) / 256, 256>>>(Whh1, Wih2, Whh2, Wih1);
    k_convx<<<(int)(((long long)Lsz * Bsz * Hsz + 255) / 256), 256>>>(x);

    // phase 1: all layer-1 input gates (parallel, tensor pipe)
    k_gi1_tc<<<dim3(H3 / 128, (Lsz * Bsz) / 128), 256, SMEM128>>>(bih1);

    // prologue: GH1 for t=0, then gates1(0) -> H1(0) in plane 0
    k_gh1_tc<<<dim3(H3 / 128, Bsz / 128), 256, SMEM128>>>(bhh1);
    k_gates1<<<Bsz, Hsz>>>();

    for (int t = 0; t < Lsz; t++) {
        k_gemm3_tc<<<256, 256, SMEM_Z0>>>(t & 1, t, bhh1, bih2, bhh2);
        k_gates2<<<Bsz, Hsz>>>(t, Wfc, bfc, out);
    }

    k_copyout<<<(Bsz * Hsz + 255) / 256, 256>>>(out, out_size);
}

// round 8
// speedup vs baseline: 1.9757x; 1.9757x over previous
#include <cuda_runtime.h>
#include <cuda_bf16.h>
#include <math.h>
#include <stdint.h>

// Problem dims
#define Bsz 512
#define Tsz 512
#define Lsz 64
#define Hsz 512
#define H3  1536                // 3*H
#define XW  (Tsz + Lsz - 1)     // 575

// ---------------- scratch (__device__ globals; no cudaMalloc) --------------
__device__ float g_GI1[(size_t)Lsz * Bsz * H3];  // [L*B][3H] fp32 (~201MB)
__device__ float g_GH1[Bsz * H3];
__device__ float g_GI2[Bsz * H3];
__device__ float g_GH2[Bsz * H3];
__device__ float g_H1[Bsz * Hsz];
__device__ float g_H2[Bsz * Hsz];

// split-bf16 planes (hi/lo)
__device__ __align__(256) __nv_bfloat16 g_Whh1h[H3 * Hsz], g_Whh1l[H3 * Hsz];
__device__ __align__(256) __nv_bfloat16 g_Wih2h[H3 * Hsz], g_Wih2l[H3 * Hsz];
__device__ __align__(256) __nv_bfloat16 g_Whh2h[H3 * Hsz], g_Whh2l[H3 * Hsz];
__device__ __align__(256) __nv_bfloat16 g_Wih1h[H3 * Hsz], g_Wih1l[H3 * Hsz];
__device__ __align__(256) __nv_bfloat16 g_H1h[Bsz * Hsz], g_H1l[Bsz * Hsz];
__device__ __align__(256) __nv_bfloat16 g_H2h[Bsz * Hsz], g_H2l[Bsz * Hsz];
// windowed x, split planes: [L*B][512]
__device__ __align__(256) __nv_bfloat16 g_Axh[(size_t)Lsz * Bsz * Hsz];
__device__ __align__(256) __nv_bfloat16 g_Axl[(size_t)Lsz * Bsz * Hsz];

// ---------------- helpers ---------------------------------------------------
__device__ __forceinline__ uint32_t smem_u32(const void* p) {
    uint32_t a;
    asm("{ .reg .u64 t; cvta.to.shared.u64 t, %1; cvt.u32.u64 %0, t; }"
        : "=r"(a) : "l"(p));
    return a;
}
__device__ __forceinline__ void cp16(uint32_t dst, const void* src) {
    asm volatile("cp.async.cg.shared.global [%0], [%1], 16;" :: "r"(dst), "l"(src));
}
__device__ __forceinline__ void ldsm4(uint32_t& r0, uint32_t& r1, uint32_t& r2, uint32_t& r3,
                                      uint32_t addr) {
    asm volatile("ldmatrix.sync.aligned.m8n8.x4.shared.b16 {%0,%1,%2,%3}, [%4];"
                 : "=r"(r0), "=r"(r1), "=r"(r2), "=r"(r3) : "r"(addr));
}
__device__ __forceinline__ void mma16816(float* c, const uint32_t* a, const uint32_t* b) {
    asm volatile(
        "mma.sync.aligned.m16n8k16.row.col.f32.bf16.bf16.f32 "
        "{%0,%1,%2,%3}, {%4,%5,%6,%7}, {%8,%9}, {%0,%1,%2,%3};"
        : "+f"(c[0]), "+f"(c[1]), "+f"(c[2]), "+f"(c[3])
        : "r"(a[0]), "r"(a[1]), "r"(a[2]), "r"(a[3]), "r"(b[0]), "r"(b[1]));
}
__device__ __forceinline__ float sigmoidf_(float v) {
    return 1.f / (1.f + __expf(-v));
}
__device__ __forceinline__ void split_store(float v, __nv_bfloat16* hp, __nv_bfloat16* lp, size_t i) {
    __nv_bfloat16 h = __float2bfloat16(v);
    hp[i] = h;
    lp[i] = __float2bfloat16(v - __bfloat162float(h));
}

#define STAGES 3

// ---------------- split-bf16 GEMM core (mma.sync, 3-stage pipeline) ---------
// D[TM x 128] = sum_{K'=1536} A'(TM x K') * B'(128 x K')^T + bias
// segments of 512: 0:(Ah,Bh) 1:(Al,Bh) 2:(Ah,Bl); chunks of BK.
// TROW = BK*2 + 16 bytes (row pad keeps ldmatrix conflict-free: TROW mod 128
// is 80 or 16 -> 8 consecutive rows hit 8 distinct 128B line offsets).
template<int TM, int BK>
__device__ __forceinline__ void gemm_mma(
    const __nv_bfloat16* __restrict__ Ah, const __nv_bfloat16* __restrict__ Al, int m0,
    const __nv_bfloat16* __restrict__ Bh, const __nv_bfloat16* __restrict__ Bl, int n0,
    const float* __restrict__ bias, float* __restrict__ C, int ldc)
{
    extern __shared__ __align__(16) char smraw[];
    constexpr int TROW  = BK * 2 + 16;
    constexpr int ATILE = TM * TROW;
    constexpr int BTILE = 128 * TROW;
    constexpr int MA    = TM / 32;
    constexpr int NCH   = 1536 / BK;       // total chunks
    constexpr int CSEG  = 512 / BK;        // chunks per segment
    constexpr int Q     = BK / 8;          // 16B quarters per row
    constexpr int RPP   = 256 / Q;         // rows loaded per pass
    const uint32_t sA = smem_u32(smraw);
    const uint32_t sB = sA + STAGES * ATILE;

    const int tid  = threadIdx.x;
    const int wid  = tid >> 5;
    const int lane = tid & 31;
    const int wm0  = (wid & 1) * (TM / 2);
    const int wn0  = (wid >> 1) * 32;

    const int qrow = tid / Q;
    const int qk   = tid % Q;

    float acc[MA][4][4];
#pragma unroll
    for (int mi = 0; mi < MA; mi++)
#pragma unroll
        for (int ni = 0; ni < 4; ni++)
#pragma unroll
            for (int j = 0; j < 4; j++) acc[mi][ni][j] = 0.f;

    auto issue = [&](int c, int st) {
        const int seg = c / CSEG;
        const int kk  = (c % CSEG) * BK;
        const __nv_bfloat16* As = (seg == 1) ? Al : Ah;
        const __nv_bfloat16* Bs = (seg == 2) ? Bl : Bh;
#pragma unroll
        for (int r = 0; r < TM; r += RPP)
            cp16(sA + st * ATILE + (qrow + r) * TROW + qk * 16,
                 As + (size_t)(m0 + qrow + r) * Hsz + kk + qk * 8);
#pragma unroll
        for (int r = 0; r < 128; r += RPP)
            cp16(sB + st * BTILE + (qrow + r) * TROW + qk * 16,
                 Bs + (size_t)(n0 + qrow + r) * Hsz + kk + qk * 8);
        asm volatile("cp.async.commit_group;");
    };

    issue(0, 0);
    issue(1, 1);

    for (int c = 0; c < NCH; c++) {
        const int st = c % STAGES;
        if (c < NCH - 1) asm volatile("cp.async.wait_group 1;");
        else             asm volatile("cp.async.wait_group 0;");
        __syncthreads();
        if (c + 2 < NCH) issue(c + 2, (c + 2) % STAGES);

        const uint32_t bufA = sA + st * ATILE;
        const uint32_t bufB = sB + st * BTILE;
#pragma unroll
        for (int kb = 0; kb < BK; kb += 16) {
            uint32_t a[MA][4];
#pragma unroll
            for (int mi = 0; mi < MA; mi++) {
                uint32_t addr = bufA + (wm0 + mi * 16 + (lane & 15)) * TROW
                              + (kb + ((lane >> 4) << 3)) * 2;
                ldsm4(a[mi][0], a[mi][1], a[mi][2], a[mi][3], addr);
            }
            uint32_t b[4][2];
#pragma unroll
            for (int nb = 0; nb < 2; nb++) {
                uint32_t addr = bufB
                              + (wn0 + nb * 16 + (lane & 7) + ((lane >> 4) << 3)) * TROW
                              + (kb + ((lane >> 3) & 1) * 8) * 2;
                uint32_t r0, r1, r2, r3;
                ldsm4(r0, r1, r2, r3, addr);
                b[nb * 2][0] = r0;     b[nb * 2][1] = r1;
                b[nb * 2 + 1][0] = r2; b[nb * 2 + 1][1] = r3;
            }
#pragma unroll
            for (int mi = 0; mi < MA; mi++)
#pragma unroll
                for (int ni = 0; ni < 4; ni++)
                    mma16816(acc[mi][ni], a[mi], b[ni]);
        }
    }

    // epilogue: direct fp32 stores + bias
#pragma unroll
    for (int mi = 0; mi < MA; mi++) {
#pragma unroll
        for (int ni = 0; ni < 4; ni++) {
            int r   = m0 + wm0 + mi * 16 + (lane >> 2);
            int cix = n0 + wn0 + ni * 8 + (lane & 3) * 2;
            float b0 = bias[cix], b1 = bias[cix + 1];
            *(float2*)&C[(size_t)r * ldc + cix] =
                make_float2(acc[mi][ni][0] + b0, acc[mi][ni][1] + b1);
            *(float2*)&C[(size_t)(r + 8) * ldc + cix] =
                make_float2(acc[mi][ni][2] + b0, acc[mi][ni][3] + b1);
        }
    }
}

#define SMEM128 (STAGES * (128 * 80) * 2)          // 61440  (TM=128, BK=32)
#define SMEM64K (STAGES * ((64 + 128) * 144))      // 82944  (TM=64,  BK=64)

// ---------------- GEMM wrappers --------------------------------------------
__global__ void __launch_bounds__(256, 2)
k_gi1_tc(const float* __restrict__ bih1)
{
    gemm_mma<128, 32>(g_Axh, g_Axl, blockIdx.y * 128,
                      g_Wih1h, g_Wih1l, blockIdx.x * 128,
                      bih1, g_GI1, H3);
}

__global__ void __launch_bounds__(256, 2)
k_gh1_tc(const float* __restrict__ bhh1)
{
    gemm_mma<128, 32>(g_H1h, g_H1l, blockIdx.y * 128,
                      g_Whh1h, g_Whh1l, blockIdx.x * 128,
                      bhh1, g_GH1, H3);
}

// per-step fused 3-GEMM, 64x128 tiles, BK=64: grid (12, 8, 3) = 288 CTAs
__global__ void __launch_bounds__(256, 2)
k_gemm3_tc(const float* __restrict__ bhh1, const float* __restrict__ bih2,
           const float* __restrict__ bhh2)
{
    const __nv_bfloat16 *Ah, *Al, *Bh, *Bl;
    const float* bias;
    float* C;
    if (blockIdx.z == 0)      { Ah = g_H1h; Al = g_H1l; Bh = g_Whh1h; Bl = g_Whh1l; bias = bhh1; C = g_GH1; }
    else if (blockIdx.z == 1) { Ah = g_H1h; Al = g_H1l; Bh = g_Wih2h; Bl = g_Wih2l; bias = bih2; C = g_GI2; }
    else                      { Ah = g_H2h; Al = g_H2l; Bh = g_Whh2h; Bl = g_Whh2l; bias = bhh2; C = g_GH2; }
    gemm_mma<64, 64>(Ah, Al, blockIdx.y * 64, Bh, Bl, blockIdx.x * 128, bias, C, H3);
}

// ---------------- elementwise ----------------------------------------------
__global__ void k_gates1(int t)
{
    int b = blockIdx.x, j = threadIdx.x;
    const float* gi = g_GI1 + ((size_t)t * Bsz + b) * H3;
    const float* gh = g_GH1 + (size_t)b * H3;
    float r = sigmoidf_(gi[j]           + gh[j]);
    float z = sigmoidf_(gi[Hsz + j]     + gh[Hsz + j]);
    float n = tanhf   (gi[2 * Hsz + j] + r * gh[2 * Hsz + j]);
    size_t hi = (size_t)b * Hsz + j;
    float h = g_H1[hi];
    float hnew = (1.f - z) * n + z * h;
    g_H1[hi] = hnew;
    split_store(hnew, g_H1h, g_H1l, hi);
}

// fused: layer-2 gates + fc output for step t, then layer-1 gates for step t+1
__global__ void k_gates12(int t, const float* __restrict__ Wfc,
                          const float* __restrict__ bfc, float* __restrict__ out)
{
    __shared__ float red[16];
    int b = blockIdx.x, j = threadIdx.x;
    int lane = j & 31, wid = j >> 5;
    size_t hi = (size_t)b * Hsz + j;

    // ---- layer 2 gates + y(t)
    {
        const float* gi = g_GI2 + (size_t)b * H3;
        const float* gh = g_GH2 + (size_t)b * H3;
        float r = sigmoidf_(gi[j]           + gh[j]);
        float z = sigmoidf_(gi[Hsz + j]     + gh[Hsz + j]);
        float n = tanhf   (gi[2 * Hsz + j] + r * gh[2 * Hsz + j]);
        float h = g_H2[hi];
        float hnew = (1.f - z) * n + z * h;
        g_H2[hi] = hnew;
        split_store(hnew, g_H2h, g_H2l, hi);

        float v = hnew * Wfc[j];
#pragma unroll
        for (int s = 16; s > 0; s >>= 1) v += __shfl_down_sync(0xffffffffu, v, s);
        if (lane == 0) red[wid] = v;
    }
    __syncthreads();
    if (wid == 0) {
        float v = (lane < 16) ? red[lane] : 0.f;
#pragma unroll
        for (int s = 8; s > 0; s >>= 1) v += __shfl_down_sync(0xffffffffu, v, s);
        if (lane == 0) out[(size_t)b * Lsz + t] = v + bfc[0];
    }

    // ---- layer 1 gates for step t+1 (GH1 was refreshed by this step's gemm3)
    if (t + 1 < Lsz) {
        const float* gi = g_GI1 + ((size_t)(t + 1) * Bsz + b) * H3;
        const float* gh = g_GH1 + (size_t)b * H3;
        float r = sigmoidf_(gi[j]           + gh[j]);
        float z = sigmoidf_(gi[Hsz + j]     + gh[Hsz + j]);
        float n = tanhf   (gi[2 * Hsz + j] + r * gh[2 * Hsz + j]);
        float h = g_H1[hi];
        float hnew = (1.f - z) * n + z * h;
        g_H1[hi] = hnew;
        split_store(hnew, g_H1h, g_H1l, hi);
    }
}

// ---------------- conversions ----------------------------------------------
__global__ void k_split_w(const float* __restrict__ Whh1, const float* __restrict__ Wih2,
                          const float* __restrict__ Whh2, const float* __restrict__ Wih1)
{
    int i = blockIdx.x * blockDim.x + threadIdx.x;
    if (i >= H3 * Hsz) return;
    split_store(Whh1[i], g_Whh1h, g_Whh1l, i);
    split_store(Wih2[i], g_Wih2h, g_Wih2l, i);
    split_store(Whh2[i], g_Whh2h, g_Whh2l, i);
    split_store(Wih1[i], g_Wih1h, g_Wih1l, i);
}

__global__ void k_convx(const float* __restrict__ x)
{
    long long i = blockIdx.x * (long long)blockDim.x + threadIdx.x;
    if (i >= (long long)Lsz * Bsz * Hsz) return;
    int k   = (int)(i & 511);
    int rem = (int)(i >> 9);
    int b   = rem & 511;
    int l   = rem >> 9;
    float v = x[(size_t)b * XW + l + k];
    split_store(v, g_Axh, g_Axl, (size_t)i);
}

__global__ void k_init(const float* __restrict__ h1in, const float* __restrict__ h2in)
{
    int i = blockIdx.x * blockDim.x + threadIdx.x;
    if (i < Bsz * Hsz) {
        float v1 = h1in[i], v2 = h2in[i];
        g_H1[i] = v1; g_H2[i] = v2;
        split_store(v1, g_H1h, g_H1l, i);
        split_store(v2, g_H2h, g_H2l, i);
    }
}

__global__ void k_copyout(float* __restrict__ out, int out_size)
{
    int i = blockIdx.x * blockDim.x + threadIdx.x;
    const int yN = Bsz * Lsz, hN = Bsz * Hsz;
    if (yN + 2 * hN <= out_size && i < hN) {
        out[yN + i]      = g_H1[i];
        out[yN + hN + i] = g_H2[i];
    }
}

// ---------------- launch ----------------------------------------------------
extern "C" void kernel_launch(void* const* d_in, const int* in_sizes, int n_in,
                              void* d_out, int out_size)
{
    const float* x    = (const float*)d_in[0];
    const float* h1in = (const float*)d_in[1];
    const float* h2in = (const float*)d_in[2];
    const float* Wih1 = (const float*)d_in[3];
    const float* Whh1 = (const float*)d_in[4];
    const float* bih1 = (const float*)d_in[5];
    const float* bhh1 = (const float*)d_in[6];
    const float* Wih2 = (const float*)d_in[7];
    const float* Whh2 = (const float*)d_in[8];
    const float* bih2 = (const float*)d_in[9];
    const float* bhh2 = (const float*)d_in[10];
    const float* Wfc  = (const float*)d_in[11];
    const float* bfc  = (const float*)d_in[12];
    float* out = (float*)d_out;

    cudaFuncSetAttribute(k_gi1_tc,   cudaFuncAttributeMaxDynamicSharedMemorySize, SMEM128);
    cudaFuncSetAttribute(k_gh1_tc,   cudaFuncAttributeMaxDynamicSharedMemorySize, SMEM128);
    cudaFuncSetAttribute(k_gemm3_tc, cudaFuncAttributeMaxDynamicSharedMemorySize, SMEM64K);

    k_init<<<(Bsz * Hsz + 255) / 256, 256>>>(h1in, h2in);
    k_split_w<<<(H3 * Hsz + 255) / 256, 256>>>(Whh1, Wih2, Whh2, Wih1);
    k_convx<<<(int)(((long long)Lsz * Bsz * Hsz + 255) / 256), 256>>>(x);

    // phase 1: all layer-1 input gates (parallel, tensor pipe)
    k_gi1_tc<<<dim3(H3 / 128, (Lsz * Bsz) / 128), 256, SMEM128>>>(bih1);

    // prologue: GH1 for t=0, then gates1(0)
    k_gh1_tc<<<dim3(H3 / 128, Bsz / 128), 256, SMEM128>>>(bhh1);
    k_gates1<<<Bsz, Hsz>>>(0);

    for (int t = 0; t < Lsz; t++) {
        // z=0: GH1(t+1) = H1 @ Whh1^T ; z=1: GI2 = H1 @ Wih2^T ; z=2: GH2 = H2 @ Whh2^T
        k_gemm3_tc<<<dim3(H3 / 128, Bsz / 64, 3), 256, SMEM64K>>>(bhh1, bih2, bhh2);
        k_gates12<<<Bsz, Hsz>>>(t, Wfc, bfc, out);
    }

    k_copyout<<<(Bsz * Hsz + 255) / 256, 256>>>(out, out_size);
}